// round 12
// baseline (speedup 1.0000x reference)
#include <cuda_runtime.h>
#include <math.h>

#define CAP 32768
#define NB  32
#define CD  64
#define TOPK 16
#define NCHUNK 2048
#define FULLM 0xFFFFFFFFu
#define ROWPAD 68

// ---------------- scratch ----------------
__device__ float g_qpart[NB * CD];
__device__ float g_qn[NB * CD];
__device__ float g_scores[NB * CAP];
__device__ float g_cmax[NB * NCHUNK];

__device__ __forceinline__ unsigned ordf(float f) {
    unsigned u = __float_as_uint(f);
    return u ^ ((unsigned)((int)u >> 31) | 0x80000000u);
}
__device__ __forceinline__ float unordf(unsigned k) {
    unsigned u = (k & 0x80000000u) ? (k ^ 0x80000000u) : ~k;
    return __uint_as_float(u);
}

// ---------------- K0: query prep (R8/R11, measured 4.5us) ----------------
__global__ __launch_bounds__(256) void k0_prep(
    const float* __restrict__ qc, const float* __restrict__ qctx,
    const float* __restrict__ W1, const float* __restrict__ b1)
{
    __shared__ float sq[64];
    __shared__ float sp[4][64];
    __shared__ float sps[2];
    int b = blockIdx.x, tid = threadIdx.x;
    int h = tid & 63, part = tid >> 6;

    if (tid < 64) sq[tid] = qc[b * CD + tid];
    float v = (tid < 64) ? qctx[b * CD + tid] : 0.0f;
    __syncthreads();

    float s = 0.0f;
    #pragma unroll
    for (int j = 0; j < 16; j++) {
        int d = part * 16 + j;
        s = fmaf(sq[d], W1[d * CD + h], s);
    }
    sp[part][h] = s;

    float ss = v * v;
    #pragma unroll
    for (int o = 16; o; o >>= 1) ss += __shfl_xor_sync(FULLM, ss, o);
    if (tid == 0)  sps[0] = ss;
    if (tid == 32) sps[1] = ss;
    __syncthreads();

    if (tid < 64) {
        g_qpart[b * CD + tid] = sp[0][tid] + sp[1][tid] + sp[2][tid] + sp[3][tid] + b1[tid];
        float inv = 1.0f / fmaxf(sqrtf(sps[0] + sps[1]), 1e-8f);
        g_qn[b * CD + tid] = v * inv;
    }
}

// ---------------- K2: fused GEMM + i-outer scoring ----------------
// dynamic smem layout:
//   [0)      sB   : 64*64 floats (W1 bottom)    16384 B
//   [16384)  sA   : 4 warps * 16*68 floats      17408 B
//   [33792)  s_w2 : 16 float4                     256 B
//   [34048)  s_qp : 32*68 floats                 8704 B
//   [42752)  s_qn : 32*68 floats                 8704 B
//   [51456)  s_inv: 4*16 floats                   256 B
#define SMEM_K2 51712

__global__ __launch_bounds__(128) void k2_fused(
    const float* __restrict__ mc, const float* __restrict__ mctx,
    const float* __restrict__ fresh,
    const float* __restrict__ W1, const float* __restrict__ W2,
    const float* __restrict__ b2p)
{
    extern __shared__ char dyn[];
    float*  sB    = (float*)dyn;
    float*  sAd   = (float*)(dyn + 16384);
    float4* s_w2  = (float4*)(dyn + 33792);
    float*  s_qp  = (float*)(dyn + 34048);
    float*  s_qn  = (float*)(dyn + 42752);
    float*  s_inv = (float*)(dyn + 51456);

    int tid = threadIdx.x, w = tid >> 5, lane = tid & 31;
    float* sAw = sAd + w * (16 * ROWPAD);

    // block-level staging: W1b, W2, qp, qn
    {
        const float4* src = (const float4*)(W1 + 64 * 64);
        float4* dst = (float4*)sB;
        for (int i = tid; i < 1024; i += 128) dst[i] = src[i];
    }
    if (tid < 16) s_w2[tid] = ((const float4*)W2)[tid];
    {
        const float4* qp4 = (const float4*)g_qpart;
        const float4* qn4 = (const float4*)g_qn;
        float4* dp = (float4*)s_qp;
        float4* dn = (float4*)s_qn;
        for (int i = tid; i < 512; i += 128) {
            int row = i >> 4, col = i & 15;
            dp[row * 17 + col] = qp4[i];
            dn[row * 17 + col] = qn4[i];
        }
    }
    __syncthreads();

    float b2v = b2p[0];

    int rg = lane >> 3;          // GEMM: 4 rows per lane
    int hg = lane & 7;           // GEMM: 8 h-cols per lane

    #pragma unroll 1
    for (int it = 0; it < 2; it++) {
        int chunk = blockIdx.x * 8 + w * 2 + it;
        int base = chunk * 16;

        __syncwarp();
        // ---- stage mc rows [16][64] ----
        {
            const float4* mcp = (const float4*)(mc + (size_t)base * CD);
            #pragma unroll
            for (int j = 0; j < 8; j++) {
                int idx = lane + 32 * j;
                int r = idx >> 4, cc = idx & 15;
                *(float4*)&sAw[r * ROWPAD + cc * 4] = mcp[idx];
            }
        }
        // ---- inv-norm pre-pass: lane pair per row (0.3 folded in) ----
        {
            int row = lane >> 1, part = lane & 1;
            const float4* mrow = (const float4*)(mctx + (size_t)(base + row) * CD + part * 32);
            float ss = 0.0f;
            #pragma unroll
            for (int j = 0; j < 8; j++) {
                float4 v = mrow[j];
                ss = fmaf(v.x, v.x, ss); ss = fmaf(v.y, v.y, ss);
                ss = fmaf(v.z, v.z, ss); ss = fmaf(v.w, v.w, ss);
            }
            ss += __shfl_xor_sync(FULLM, ss, 1);
            if (part == 0) s_inv[w * 16 + row] = 0.3f / fmaxf(sqrtf(ss), 1e-8f);
        }
        __syncwarp();

        // ---- GEMM: m_part[r][h] = sum_d mc[r][d] * W1b[d][h] (R11 verbatim) ----
        {
            float acc[4][8];
            #pragma unroll
            for (int r = 0; r < 4; r++)
                #pragma unroll
                for (int j = 0; j < 8; j++) acc[r][j] = 0.0f;

            #pragma unroll 4
            for (int d4 = 0; d4 < 16; d4++) {
                float4 a[4];
                #pragma unroll
                for (int r = 0; r < 4; r++)
                    a[r] = *(const float4*)&sAw[(rg * 4 + r) * ROWPAD + d4 * 4];
                #pragma unroll
                for (int k = 0; k < 4; k++) {
                    int d = 4 * d4 + k;
                    float4 blo = *(const float4*)&sB[d * 64 + hg * 8];
                    float4 bhi = *(const float4*)&sB[d * 64 + hg * 8 + 4];
                    #pragma unroll
                    for (int r = 0; r < 4; r++) {
                        float av = (k == 0) ? a[r].x : (k == 1) ? a[r].y : (k == 2) ? a[r].z : a[r].w;
                        acc[r][0] = fmaf(av, blo.x, acc[r][0]);
                        acc[r][1] = fmaf(av, blo.y, acc[r][1]);
                        acc[r][2] = fmaf(av, blo.z, acc[r][2]);
                        acc[r][3] = fmaf(av, blo.w, acc[r][3]);
                        acc[r][4] = fmaf(av, bhi.x, acc[r][4]);
                        acc[r][5] = fmaf(av, bhi.y, acc[r][5]);
                        acc[r][6] = fmaf(av, bhi.z, acc[r][6]);
                        acc[r][7] = fmaf(av, bhi.w, acc[r][7]);
                    }
                }
            }
            __syncwarp();
            #pragma unroll
            for (int r = 0; r < 4; r++) {
                *(float4*)&sAw[(rg * 4 + r) * ROWPAD + hg * 8] =
                    make_float4(acc[r][0], acc[r][1], acc[r][2], acc[r][3]);
                *(float4*)&sAw[(rg * 4 + r) * ROWPAD + hg * 8 + 4] =
                    make_float4(acc[r][4], acc[r][5], acc[r][6], acc[r][7]);
            }
            __syncwarp();
        }

        float sc16[16];

        // ---- MLP pass, i-outer: w2/qp fetched once per i ----
        {
            float acc[16];
            #pragma unroll
            for (int r = 0; r < 16; r++) acc[r] = 0.0f;

            #pragma unroll 4
            for (int i = 0; i < 16; i++) {
                float4 w2 = s_w2[i];
                float4 qpi = ((const float4*)s_qp)[lane * 17 + i];
                #pragma unroll
                for (int r = 0; r < 16; r++) {
                    float4 mp = *(const float4*)&sAw[r * ROWPAD + 4 * i];
                    float t0 = fmaxf(qpi.x + mp.x, 0.0f);
                    float t1 = fmaxf(qpi.y + mp.y, 0.0f);
                    float t2 = fmaxf(qpi.z + mp.z, 0.0f);
                    float t3 = fmaxf(qpi.w + mp.w, 0.0f);
                    float a = fmaf(t0, w2.x, acc[r]);
                    a = fmaf(t1, w2.y, a);
                    a = fmaf(t2, w2.z, a);
                    acc[r] = fmaf(t3, w2.w, a);
                }
            }
            #pragma unroll
            for (int r = 0; r < 16; r++) {
                float z = acc[r] + b2v;
                float sig = 1.0f / (1.0f + __expf(-z));
                sc16[r] = fmaf(0.5f, sig, 0.2f * fresh[base + r]);
            }
        }

        // ---- ctx pass, i-outer: mctx via lane-uniform LDG ----
        {
            float xac[16];
            #pragma unroll
            for (int r = 0; r < 16; r++) xac[r] = 0.0f;

            #pragma unroll 4
            for (int i = 0; i < 16; i++) {
                float4 qni = ((const float4*)s_qn)[lane * 17 + i];
                #pragma unroll
                for (int r = 0; r < 16; r++) {
                    float4 mx = *(const float4*)(mctx + (size_t)(base + r) * CD + 4 * i);
                    float a = fmaf(qni.x, mx.x, xac[r]);
                    a = fmaf(qni.y, mx.y, a);
                    a = fmaf(qni.z, mx.z, a);
                    xac[r] = fmaf(qni.w, mx.w, a);
                }
            }
            float cmax = -1e30f;
            #pragma unroll
            for (int r = 0; r < 16; r++) {
                sc16[r] = fmaf(xac[r], s_inv[w * 16 + r], sc16[r]);
                cmax = fmaxf(cmax, sc16[r]);
            }
            #pragma unroll
            for (int pp = 0; pp < 4; pp++) {
                *(float4*)&g_scores[(size_t)lane * CAP + base + 4 * pp] =
                    make_float4(sc16[4 * pp], sc16[4 * pp + 1], sc16[4 * pp + 2], sc16[4 * pp + 3]);
            }
            g_cmax[lane * NCHUNK + chunk] = cmax;
        }
    }
}

// ---------------- K3: threshold-filter top-16 + gather ----------------
__global__ __launch_bounds__(256) void k3_topk(
    const float* __restrict__ mc, const float* __restrict__ fresh,
    float* __restrict__ out)
{
    __shared__ unsigned s_key[NCHUNK];
    __shared__ unsigned s_tm[256];
    __shared__ unsigned s_tau;
    __shared__ int s_cnt, s_cnt2;
    __shared__ int s_cand[64];
    __shared__ unsigned s_ekey[64];
    __shared__ int s_eidx[64];
    __shared__ int s_sel[TOPK];
    __shared__ float s_val[TOPK];

    int b = blockIdx.x;
    int tid = threadIdx.x;
    int lane = tid & 31;

    unsigned tmax = 0;
    #pragma unroll
    for (int j = 0; j < 8; j++) {
        unsigned k = ordf(g_cmax[b * NCHUNK + tid * 8 + j]);
        s_key[tid * 8 + j] = k;
        tmax = max(tmax, k);
    }
    s_tm[tid] = tmax;
    if (tid == 0) { s_cnt = 0; s_cnt2 = 0; }
    if (tid < 64) s_ekey[tid] = 0u;
    __syncthreads();

    if (tid < 32) {
        unsigned gm = 0;
        #pragma unroll
        for (int j = 0; j < 8; j++) gm = max(gm, s_tm[lane * 8 + j]);
        int rank = 0;
        #pragma unroll
        for (int j = 0; j < 32; j++) {
            unsigned vj = __shfl_sync(FULLM, gm, j);
            rank += (vj > gm) || (vj == gm && j < lane);
        }
        unsigned eq = __ballot_sync(FULLM, rank == 15);
        unsigned tau = __shfl_sync(FULLM, gm, __ffs(eq) - 1);
        if (lane == 0) s_tau = tau;
    }
    __syncthreads();
    unsigned tau = s_tau;

    #pragma unroll
    for (int j = 0; j < 8; j++) {
        int ch = tid * 8 + j;
        if (s_key[ch] >= tau) {
            int p = atomicAdd(&s_cnt, 1);
            if (p < 64) s_cand[p] = ch;
        }
    }
    __syncthreads();
    int cnt = min(s_cnt, 64);

    for (int i = tid; i < cnt * 16; i += 256) {
        int ch = s_cand[i >> 4];
        int gi = ch * 16 + (i & 15);
        unsigned key = ordf(g_scores[(size_t)b * CAP + gi]);
        if (key >= tau) {
            int p = atomicAdd(&s_cnt2, 1);
            if (p < 64) { s_ekey[p] = key; s_eidx[p] = gi; }
        }
    }
    __syncthreads();

    if (tid < 32) {
        for (int k = 0; k < TOPK; k++) {
            unsigned lkey = 0; int lidx = 0x7FFFFFFF; int lpos = -1;
            #pragma unroll
            for (int j = 0; j < 2; j++) {
                int p = lane + 32 * j;
                unsigned kk = s_ekey[p];
                int ii = s_eidx[p];
                if (kk > lkey || (kk == lkey && kk != 0u && ii < lidx)) {
                    lkey = kk; lidx = ii; lpos = p;
                }
            }
            unsigned m = __reduce_max_sync(FULLM, lkey);
            int cand = (lkey == m) ? lidx : 0x7FFFFFFF;
            int gi = __reduce_min_sync(FULLM, cand);
            if (lane == 0) { s_sel[k] = gi; s_val[k] = unordf(m); }
            if (lkey == m && lidx == gi) s_ekey[lpos] = 0u;
            __syncwarp();
        }
    }
    __syncthreads();

    for (int i = tid; i < TOPK * CD; i += 256) {
        int k = i >> 6, h = i & 63;
        out[(size_t)b * (TOPK * CD) + i] = mc[(size_t)s_sel[k] * CD + h];
    }
    if (tid < TOPK) {
        out[NB * TOPK * CD + b * TOPK + tid] = s_val[tid];
        out[NB * TOPK * CD + NB * TOPK + b * TOPK + tid] = fresh[s_sel[tid]];
    }
}

// ---------------- launch ----------------
extern "C" void kernel_launch(void* const* d_in, const int* in_sizes, int n_in,
                              void* d_out, int out_size)
{
    const float* qc    = (const float*)d_in[0];
    const float* qctx  = (const float*)d_in[1];
    const float* mc    = (const float*)d_in[2];
    const float* mctx  = (const float*)d_in[3];
    const float* fresh = (const float*)d_in[4];
    const float* W1    = (const float*)d_in[5];
    const float* b1    = (const float*)d_in[6];
    const float* W2    = (const float*)d_in[7];
    const float* b2    = (const float*)d_in[8];
    float* out = (float*)d_out;

    cudaFuncSetAttribute(k2_fused, cudaFuncAttributeMaxDynamicSharedMemorySize, SMEM_K2);

    k0_prep<<<NB, 256>>>(qc, qctx, W1, b1);
    k2_fused<<<NCHUNK / 8, 128, SMEM_K2>>>(mc, mctx, fresh, W1, W2, b2);
    k3_topk<<<NB, 256>>>(mc, fresh, out);
}

// round 13
// speedup vs baseline: 1.1032x; 1.1032x over previous
#include <cuda_runtime.h>
#include <math.h>

#define CAP 32768
#define NB  32
#define CD  64
#define TOPK 16
#define NCHUNK 2048
#define FULLM 0xFFFFFFFFu
#define ROWPAD 68
#define QPITCH 68

// ---------------- scratch ----------------
__device__ float g_qpart[NB * CD];
__device__ float g_qn[NB * CD];
__device__ float g_scores[NB * CAP];
__device__ float g_cmax[NB * NCHUNK];

__device__ __forceinline__ unsigned ordf(float f) {
    unsigned u = __float_as_uint(f);
    return u ^ ((unsigned)((int)u >> 31) | 0x80000000u);
}
__device__ __forceinline__ float unordf(unsigned k) {
    unsigned u = (k & 0x80000000u) ? (k ^ 0x80000000u) : ~k;
    return __uint_as_float(u);
}

// ---------------- K0: query prep (R8, measured ~4.5us) ----------------
__global__ __launch_bounds__(256) void k0_prep(
    const float* __restrict__ qc, const float* __restrict__ qctx,
    const float* __restrict__ W1, const float* __restrict__ b1)
{
    __shared__ float sq[64];
    __shared__ float sp[4][64];
    __shared__ float sps[2];
    int b = blockIdx.x, tid = threadIdx.x;
    int h = tid & 63, part = tid >> 6;

    if (tid < 64) sq[tid] = qc[b * CD + tid];
    float v = (tid < 64) ? qctx[b * CD + tid] : 0.0f;
    __syncthreads();

    float s = 0.0f;
    #pragma unroll
    for (int j = 0; j < 16; j++) {
        int d = part * 16 + j;
        s = fmaf(sq[d], W1[d * CD + h], s);
    }
    sp[part][h] = s;

    float ss = v * v;
    #pragma unroll
    for (int o = 16; o; o >>= 1) ss += __shfl_xor_sync(FULLM, ss, o);
    if (tid == 0)  sps[0] = ss;
    if (tid == 32) sps[1] = ss;
    __syncthreads();

    if (tid < 64) {
        g_qpart[b * CD + tid] = sp[0][tid] + sp[1][tid] + sp[2][tid] + sp[3][tid] + b1[tid];
        float inv = 1.0f / fmaxf(sqrtf(sps[0] + sps[1]), 1e-8f);
        g_qn[b * CD + tid] = v * inv;
    }
}

// ---------------- K2: fused GEMM + scoring; qp/qn in block smem ----------------
// dynamic smem layout:
//   [0)      sB   : 64*64 floats                 16384 B
//   [16384)  sA   : 4 warps * 16*68 floats       17408 B
//   [33792)  s_qp : 32*QPITCH floats              8704 B
//   [42496)  s_qn : 32*QPITCH floats              8704 B
//   [51200)  s_mx : 4*2*16 float4                 2048 B
//   [53248)  s_w2 : 16 float4                      256 B
//   [53504)  s_inv: 8 floats                        32 B
#define SMEM_K2 53536

__global__ __launch_bounds__(128) void k2_fused(
    const float* __restrict__ mc, const float* __restrict__ mctx,
    const float* __restrict__ fresh,
    const float* __restrict__ W1, const float* __restrict__ W2,
    const float* __restrict__ b2p)
{
    extern __shared__ char dyn[];
    float*  sB    = (float*)dyn;
    float*  sAd   = (float*)(dyn + 16384);
    float*  s_qp  = (float*)(dyn + 33792);
    float*  s_qn  = (float*)(dyn + 42496);
    float4* s_mx  = (float4*)(dyn + 51200);
    float4* s_w2  = (float4*)(dyn + 53248);
    float*  s_inv = (float*)(dyn + 53504);

    int tid = threadIdx.x, w = tid >> 5, lane = tid & 31;
    float* sAw = sAd + w * (16 * ROWPAD);

    // block staging: W1b, W2, qp, qn
    {
        const float4* src = (const float4*)(W1 + 64 * 64);
        float4* dst = (float4*)sB;
        for (int i = tid; i < 1024; i += 128) dst[i] = src[i];
    }
    if (tid < 16) s_w2[tid] = ((const float4*)W2)[tid];
    {
        const float4* qp4 = (const float4*)g_qpart;
        const float4* qn4 = (const float4*)g_qn;
        for (int i = tid; i < 512; i += 128) {
            int row = i >> 4, col = i & 15;
            *(float4*)&s_qp[row * QPITCH + col * 4] = qp4[i];
            *(float4*)&s_qn[row * QPITCH + col * 4] = qn4[i];
        }
    }
    __syncthreads();

    float b2v = b2p[0];

    int rg = lane >> 3;
    int hg = lane & 7;
    int half = lane >> 4, q = lane & 15;

    #pragma unroll 1
    for (int it = 0; it < 2; it++) {
        int chunk = blockIdx.x * 8 + w * 2 + it;
        int base = chunk * 16;

        __syncwarp();
        // stage mc rows [16][64]
        {
            const float4* mcp = (const float4*)(mc + (size_t)base * CD);
            #pragma unroll
            for (int j = 0; j < 8; j++) {
                int idx = lane + 32 * j;
                int r = idx >> 4, cc = idx & 15;
                *(float4*)&sAw[r * ROWPAD + cc * 4] = mcp[idx];
            }
        }
        __syncwarp();

        // GEMM: m_part[r][h] = sum_d mc[r][d] * W1b[d][h]
        {
            float acc[4][8];
            #pragma unroll
            for (int r = 0; r < 4; r++)
                #pragma unroll
                for (int j = 0; j < 8; j++) acc[r][j] = 0.0f;

            #pragma unroll 4
            for (int d4 = 0; d4 < 16; d4++) {
                float4 a[4];
                #pragma unroll
                for (int r = 0; r < 4; r++)
                    a[r] = *(const float4*)&sAw[(rg * 4 + r) * ROWPAD + d4 * 4];
                #pragma unroll
                for (int k = 0; k < 4; k++) {
                    int d = 4 * d4 + k;
                    float4 blo = *(const float4*)&sB[d * 64 + hg * 8];
                    float4 bhi = *(const float4*)&sB[d * 64 + hg * 8 + 4];
                    #pragma unroll
                    for (int r = 0; r < 4; r++) {
                        float av = (k == 0) ? a[r].x : (k == 1) ? a[r].y : (k == 2) ? a[r].z : a[r].w;
                        acc[r][0] = fmaf(av, blo.x, acc[r][0]);
                        acc[r][1] = fmaf(av, blo.y, acc[r][1]);
                        acc[r][2] = fmaf(av, blo.z, acc[r][2]);
                        acc[r][3] = fmaf(av, blo.w, acc[r][3]);
                        acc[r][4] = fmaf(av, bhi.x, acc[r][4]);
                        acc[r][5] = fmaf(av, bhi.y, acc[r][5]);
                        acc[r][6] = fmaf(av, bhi.z, acc[r][6]);
                        acc[r][7] = fmaf(av, bhi.w, acc[r][7]);
                    }
                }
            }
            __syncwarp();
            #pragma unroll
            for (int r = 0; r < 4; r++) {
                *(float4*)&sAw[(rg * 4 + r) * ROWPAD + hg * 8] =
                    make_float4(acc[r][0], acc[r][1], acc[r][2], acc[r][3]);
                *(float4*)&sAw[(rg * 4 + r) * ROWPAD + hg * 8 + 4] =
                    make_float4(acc[r][4], acc[r][5], acc[r][6], acc[r][7]);
            }
            __syncwarp();
        }

        // scoring: 16 rows, 2 at a time; lane = query b; qp/qn read from smem per i
        float4 nmx = ((const float4*)(mctx + (size_t)(base + half) * CD))[q];
        float cmax = -1e30f;

        #pragma unroll 1
        for (int pp = 0; pp < 4; pp++) {
            float out4[4];
            #pragma unroll
            for (int p2 = 0; p2 < 2; p2++) {
                int p = 2 * pp + p2;
                int c0 = base + 2 * p;
                s_mx[(w * 2 + half) * 16 + q] = nmx;
                float ssn = nmx.x * nmx.x + nmx.y * nmx.y + nmx.z * nmx.z + nmx.w * nmx.w;
                ssn += __shfl_xor_sync(FULLM, ssn, 1);
                ssn += __shfl_xor_sync(FULLM, ssn, 2);
                ssn += __shfl_xor_sync(FULLM, ssn, 4);
                ssn += __shfl_xor_sync(FULLM, ssn, 8);
                if (q == 0) s_inv[w * 2 + half] = 1.0f / fmaxf(sqrtf(ssn), 1e-8f);
                __syncwarp();
                if (p < 7)
                    nmx = ((const float4*)(mctx + (size_t)(c0 + 2 + half) * CD))[q];
                #pragma unroll
                for (int r = 0; r < 2; r++) {
                    int c = c0 + r;
                    int rl = 2 * p + r;
                    float ac0 = 0.f, ac1 = 0.f, ac2 = 0.f, ac3 = 0.f;
                    float ax0 = 0.f, ax1 = 0.f, ax2 = 0.f, ax3 = 0.f;
                    #pragma unroll
                    for (int i = 0; i < 16; i++) {
                        float4 qpi = *(const float4*)&s_qp[lane * QPITCH + 4 * i];
                        float4 qni = *(const float4*)&s_qn[lane * QPITCH + 4 * i];
                        float4 mp = *(const float4*)&sAw[rl * ROWPAD + 4 * i];
                        float4 mx = s_mx[(w * 2 + r) * 16 + i];
                        float4 w2 = s_w2[i];
                        float t0 = fmaxf(qpi.x + mp.x, 0.0f);
                        float t1 = fmaxf(qpi.y + mp.y, 0.0f);
                        float t2 = fmaxf(qpi.z + mp.z, 0.0f);
                        float t3 = fmaxf(qpi.w + mp.w, 0.0f);
                        ac0 = fmaf(t0, w2.x, ac0);
                        ac1 = fmaf(t1, w2.y, ac1);
                        ac2 = fmaf(t2, w2.z, ac2);
                        ac3 = fmaf(t3, w2.w, ac3);
                        ax0 = fmaf(qni.x, mx.x, ax0);
                        ax1 = fmaf(qni.y, mx.y, ax1);
                        ax2 = fmaf(qni.z, mx.z, ax2);
                        ax3 = fmaf(qni.w, mx.w, ax3);
                    }
                    float z   = (ac0 + ac1) + (ac2 + ac3) + b2v;
                    float ctx = ((ax0 + ax1) + (ax2 + ax3)) * s_inv[w * 2 + r];
                    float sig = 1.0f / (1.0f + __expf(-z));
                    float score = 0.5f * sig + 0.3f * ctx + 0.2f * fresh[c];
                    out4[2 * p2 + r] = score;
                    cmax = fmaxf(cmax, score);
                }
                __syncwarp();
            }
            *(float4*)&g_scores[(size_t)lane * CAP + base + 4 * pp] =
                make_float4(out4[0], out4[1], out4[2], out4[3]);
        }
        g_cmax[lane * NCHUNK + chunk] = cmax;
    }
}

// ---------------- K3: threshold-filter top-16 + gather ----------------
__global__ __launch_bounds__(256) void k3_topk(
    const float* __restrict__ mc, const float* __restrict__ fresh,
    float* __restrict__ out)
{
    __shared__ unsigned s_key[NCHUNK];
    __shared__ unsigned s_tm[256];
    __shared__ unsigned s_tau;
    __shared__ int s_cnt, s_cnt2;
    __shared__ int s_cand[64];
    __shared__ unsigned s_ekey[64];
    __shared__ int s_eidx[64];
    __shared__ int s_sel[TOPK];
    __shared__ float s_val[TOPK];

    int b = blockIdx.x;
    int tid = threadIdx.x;
    int lane = tid & 31;

    unsigned tmax = 0;
    #pragma unroll
    for (int j = 0; j < 8; j++) {
        unsigned k = ordf(g_cmax[b * NCHUNK + tid * 8 + j]);
        s_key[tid * 8 + j] = k;
        tmax = max(tmax, k);
    }
    s_tm[tid] = tmax;
    if (tid == 0) { s_cnt = 0; s_cnt2 = 0; }
    if (tid < 64) s_ekey[tid] = 0u;
    __syncthreads();

    if (tid < 32) {
        unsigned gm = 0;
        #pragma unroll
        for (int j = 0; j < 8; j++) gm = max(gm, s_tm[lane * 8 + j]);
        int rank = 0;
        #pragma unroll
        for (int j = 0; j < 32; j++) {
            unsigned vj = __shfl_sync(FULLM, gm, j);
            rank += (vj > gm) || (vj == gm && j < lane);
        }
        unsigned eq = __ballot_sync(FULLM, rank == 15);
        unsigned tau = __shfl_sync(FULLM, gm, __ffs(eq) - 1);
        if (lane == 0) s_tau = tau;
    }
    __syncthreads();
    unsigned tau = s_tau;

    #pragma unroll
    for (int j = 0; j < 8; j++) {
        int ch = tid * 8 + j;
        if (s_key[ch] >= tau) {
            int p = atomicAdd(&s_cnt, 1);
            if (p < 64) s_cand[p] = ch;
        }
    }
    __syncthreads();
    int cnt = min(s_cnt, 64);

    for (int i = tid; i < cnt * 16; i += 256) {
        int ch = s_cand[i >> 4];
        int gi = ch * 16 + (i & 15);
        unsigned key = ordf(g_scores[(size_t)b * CAP + gi]);
        if (key >= tau) {
            int p = atomicAdd(&s_cnt2, 1);
            if (p < 64) { s_ekey[p] = key; s_eidx[p] = gi; }
        }
    }
    __syncthreads();

    if (tid < 32) {
        for (int k = 0; k < TOPK; k++) {
            unsigned lkey = 0; int lidx = 0x7FFFFFFF; int lpos = -1;
            #pragma unroll
            for (int j = 0; j < 2; j++) {
                int p = lane + 32 * j;
                unsigned kk = s_ekey[p];
                int ii = s_eidx[p];
                if (kk > lkey || (kk == lkey && kk != 0u && ii < lidx)) {
                    lkey = kk; lidx = ii; lpos = p;
                }
            }
            unsigned m = __reduce_max_sync(FULLM, lkey);
            int cand = (lkey == m) ? lidx : 0x7FFFFFFF;
            int gi = __reduce_min_sync(FULLM, cand);
            if (lane == 0) { s_sel[k] = gi; s_val[k] = unordf(m); }
            if (lkey == m && lidx == gi) s_ekey[lpos] = 0u;
            __syncwarp();
        }
    }
    __syncthreads();

    for (int i = tid; i < TOPK * CD; i += 256) {
        int k = i >> 6, h = i & 63;
        out[(size_t)b * (TOPK * CD) + i] = mc[(size_t)s_sel[k] * CD + h];
    }
    if (tid < TOPK) {
        out[NB * TOPK * CD + b * TOPK + tid] = s_val[tid];
        out[NB * TOPK * CD + NB * TOPK + b * TOPK + tid] = fresh[s_sel[tid]];
    }
}

// ---------------- launch ----------------
extern "C" void kernel_launch(void* const* d_in, const int* in_sizes, int n_in,
                              void* d_out, int out_size)
{
    const float* qc    = (const float*)d_in[0];
    const float* qctx  = (const float*)d_in[1];
    const float* mc    = (const float*)d_in[2];
    const float* mctx  = (const float*)d_in[3];
    const float* fresh = (const float*)d_in[4];
    const float* W1    = (const float*)d_in[5];
    const float* b1    = (const float*)d_in[6];
    const float* W2    = (const float*)d_in[7];
    const float* b2    = (const float*)d_in[8];
    float* out = (float*)d_out;

    cudaFuncSetAttribute(k2_fused, cudaFuncAttributeMaxDynamicSharedMemorySize, SMEM_K2);

    k0_prep<<<NB, 256>>>(qc, qctx, W1, b1);
    k2_fused<<<NCHUNK / 8, 128, SMEM_K2>>>(mc, mctx, fresh, W1, W2, b2);
    k3_topk<<<NB, 256>>>(mc, fresh, out);
}

// round 15
// speedup vs baseline: 1.1873x; 1.0763x over previous
#include <cuda_runtime.h>
#include <math.h>

#define CAP 32768
#define NB  32
#define CD  64
#define TOPK 16
#define NCHUNK 2048
#define FULLM 0xFFFFFFFFu
#define ROWPAD 68

// ---------------- scratch ----------------
__device__ float g_qpart[NB * CD];
__device__ float g_qn[NB * CD];
__device__ float g_s1qp[NB];          // w2 . qpart[b]  (rank-1 MLP term)
__device__ float g_scores[NB * CAP];
__device__ float g_cmax[NB * NCHUNK];

__device__ __forceinline__ unsigned ordf(float f) {
    unsigned u = __float_as_uint(f);
    return u ^ ((unsigned)((int)u >> 31) | 0x80000000u);
}
__device__ __forceinline__ float unordf(unsigned k) {
    unsigned u = (k & 0x80000000u) ? (k ^ 0x80000000u) : ~k;
    return __uint_as_float(u);
}

// ---------------- K0: query prep + s1qp ----------------
__global__ __launch_bounds__(256) void k0_prep(
    const float* __restrict__ qc, const float* __restrict__ qctx,
    const float* __restrict__ W1, const float* __restrict__ b1,
    const float* __restrict__ W2)
{
    __shared__ float sq[64];
    __shared__ float sp[4][64];
    __shared__ float sps[2];
    __shared__ float sd[2];
    int b = blockIdx.x, tid = threadIdx.x;
    int h = tid & 63, part = tid >> 6;

    if (tid < 64) sq[tid] = qc[b * CD + tid];
    float v = (tid < 64) ? qctx[b * CD + tid] : 0.0f;
    __syncthreads();

    float s = 0.0f;
    #pragma unroll
    for (int j = 0; j < 16; j++) {
        int d = part * 16 + j;
        s = fmaf(sq[d], W1[d * CD + h], s);
    }
    sp[part][h] = s;

    float ss = v * v;
    #pragma unroll
    for (int o = 16; o; o >>= 1) ss += __shfl_xor_sync(FULLM, ss, o);
    if (tid == 0)  sps[0] = ss;
    if (tid == 32) sps[1] = ss;
    __syncthreads();

    if (tid < 64) {
        float qv = sp[0][tid] + sp[1][tid] + sp[2][tid] + sp[3][tid] + b1[tid];
        g_qpart[b * CD + tid] = qv;
        float inv = 1.0f / fmaxf(sqrtf(sps[0] + sps[1]), 1e-8f);
        g_qn[b * CD + tid] = v * inv;
        // s1qp partial: w2[h] * qpart[b][h]
        float c1 = qv * W2[tid];
        #pragma unroll
        for (int o = 16; o; o >>= 1) c1 += __shfl_xor_sync(FULLM, c1, o);
        if (tid == 0)  sd[0] = c1;
        if (tid == 32) sd[1] = c1;
    }
    __syncthreads();
    if (tid == 0) g_s1qp[b] = sd[0] + sd[1];
}

// ---------------- K2: fused GEMM + scoring (abs-trick MLP) ----------------
__global__ __launch_bounds__(128, 1) void k2_fused(
    const float* __restrict__ mc, const float* __restrict__ mctx,
    const float* __restrict__ fresh,
    const float* __restrict__ W1, const float* __restrict__ W2,
    const float* __restrict__ b2p)
{
    __shared__ float  sB[64 * 64];
    __shared__ float  sA[4][16 * ROWPAD];
    __shared__ float4 s_mx[4][2][16];
    __shared__ float4 s_w2[16];
    __shared__ float  s_inv[4][2];
    __shared__ float  s_s1m[4][16];

    int tid = threadIdx.x, w = tid >> 5, lane = tid & 31;

    {
        const float4* src = (const float4*)(W1 + 64 * 64);
        float4* dst = (float4*)sB;
        for (int i = tid; i < 1024; i += 128) dst[i] = src[i];
    }
    if (tid < 16) s_w2[tid] = ((const float4*)W2)[tid];
    __syncthreads();

    float b2v = b2p[0];
    float s1qp_lane = g_s1qp[lane];

    float qp[64], qn[64];
    {
        const float4* a4 = (const float4*)(g_qpart + lane * CD);
        const float4* n4 = (const float4*)(g_qn + lane * CD);
        #pragma unroll
        for (int i = 0; i < 16; i++) {
            float4 a = a4[i];
            qp[4 * i + 0] = a.x; qp[4 * i + 1] = a.y; qp[4 * i + 2] = a.z; qp[4 * i + 3] = a.w;
            float4 n = n4[i];
            qn[4 * i + 0] = n.x; qn[4 * i + 1] = n.y; qn[4 * i + 2] = n.z; qn[4 * i + 3] = n.w;
        }
    }

    int rg = lane >> 3;
    int hg = lane & 7;
    int half = lane >> 4, q = lane & 15;

    #pragma unroll 1
    for (int it = 0; it < 2; it++) {
        int chunk = blockIdx.x * 8 + w * 2 + it;
        int base = chunk * 16;

        __syncwarp();
        // stage mc rows [16][64]
        {
            const float4* mcp = (const float4*)(mc + (size_t)base * CD);
            #pragma unroll
            for (int j = 0; j < 8; j++) {
                int idx = lane + 32 * j;
                int r = idx >> 4, cc = idx & 15;
                *(float4*)&sA[w][r * ROWPAD + cc * 4] = mcp[idx];
            }
        }
        __syncwarp();

        // GEMM: m_part[r][h] = sum_d mc[r][d] * W1b[d][h]
        float acc[4][8];
        #pragma unroll
        for (int r = 0; r < 4; r++)
            #pragma unroll
            for (int j = 0; j < 8; j++) acc[r][j] = 0.0f;

        #pragma unroll 4
        for (int d4 = 0; d4 < 16; d4++) {
            float4 a[4];
            #pragma unroll
            for (int r = 0; r < 4; r++)
                a[r] = *(const float4*)&sA[w][(rg * 4 + r) * ROWPAD + d4 * 4];
            #pragma unroll
            for (int k = 0; k < 4; k++) {
                int d = 4 * d4 + k;
                float4 blo = *(const float4*)&sB[d * 64 + hg * 8];
                float4 bhi = *(const float4*)&sB[d * 64 + hg * 8 + 4];
                #pragma unroll
                for (int r = 0; r < 4; r++) {
                    float av = (k == 0) ? a[r].x : (k == 1) ? a[r].y : (k == 2) ? a[r].z : a[r].w;
                    acc[r][0] = fmaf(av, blo.x, acc[r][0]);
                    acc[r][1] = fmaf(av, blo.y, acc[r][1]);
                    acc[r][2] = fmaf(av, blo.z, acc[r][2]);
                    acc[r][3] = fmaf(av, blo.w, acc[r][3]);
                    acc[r][4] = fmaf(av, bhi.x, acc[r][4]);
                    acc[r][5] = fmaf(av, bhi.y, acc[r][5]);
                    acc[r][6] = fmaf(av, bhi.z, acc[r][6]);
                    acc[r][7] = fmaf(av, bhi.w, acc[r][7]);
                }
            }
        }
        __syncwarp();
        // write m_part + compute s1m[r] = w2 . m_part[r] from resident accumulators
        {
            float4 w2lo = s_w2[hg * 2];
            float4 w2hi = s_w2[hg * 2 + 1];
            #pragma unroll
            for (int r = 0; r < 4; r++) {
                *(float4*)&sA[w][(rg * 4 + r) * ROWPAD + hg * 8] =
                    make_float4(acc[r][0], acc[r][1], acc[r][2], acc[r][3]);
                *(float4*)&sA[w][(rg * 4 + r) * ROWPAD + hg * 8 + 4] =
                    make_float4(acc[r][4], acc[r][5], acc[r][6], acc[r][7]);
                float sp = acc[r][0] * w2lo.x;
                sp = fmaf(acc[r][1], w2lo.y, sp);
                sp = fmaf(acc[r][2], w2lo.z, sp);
                sp = fmaf(acc[r][3], w2lo.w, sp);
                sp = fmaf(acc[r][4], w2hi.x, sp);
                sp = fmaf(acc[r][5], w2hi.y, sp);
                sp = fmaf(acc[r][6], w2hi.z, sp);
                sp = fmaf(acc[r][7], w2hi.w, sp);
                sp += __shfl_xor_sync(FULLM, sp, 1);
                sp += __shfl_xor_sync(FULLM, sp, 2);
                sp += __shfl_xor_sync(FULLM, sp, 4);
                if (hg == 0) s_s1m[w][rg * 4 + r] = sp;
            }
        }
        __syncwarp();

        // scoring: 16 rows, 2 at a time; lane = query b
        float4 nmx = ((const float4*)(mctx + (size_t)(base + half) * CD))[q];
        float cmax = -1e30f;

        #pragma unroll 1
        for (int pp = 0; pp < 4; pp++) {
            float out4[4];
            #pragma unroll
            for (int p2 = 0; p2 < 2; p2++) {
                int p = 2 * pp + p2;
                int c0 = base + 2 * p;
                s_mx[w][half][q] = nmx;
                float ssn = nmx.x * nmx.x + nmx.y * nmx.y + nmx.z * nmx.z + nmx.w * nmx.w;
                ssn += __shfl_xor_sync(FULLM, ssn, 1);
                ssn += __shfl_xor_sync(FULLM, ssn, 2);
                ssn += __shfl_xor_sync(FULLM, ssn, 4);
                ssn += __shfl_xor_sync(FULLM, ssn, 8);
                if (q == 0) s_inv[w][half] = 1.0f / fmaxf(sqrtf(ssn), 1e-8f);
                __syncwarp();
                if (p < 7)
                    nmx = ((const float4*)(mctx + (size_t)(c0 + 2 + half) * CD))[q];
                #pragma unroll
                for (int r = 0; r < 2; r++) {
                    int c = c0 + r;
                    int rl = 2 * p + r;
                    float ac0 = 0.f, ac1 = 0.f, ac2 = 0.f, ac3 = 0.f;
                    float ax0 = 0.f, ax1 = 0.f, ax2 = 0.f, ax3 = 0.f;
                    #pragma unroll
                    for (int i = 0; i < 16; i++) {
                        float4 mp = *(const float4*)&sA[w][rl * ROWPAD + 4 * i];
                        float4 mx = s_mx[w][r][i];
                        float4 w2 = s_w2[i];
                        // S2 = sum w2*|qp+mp|  (abs modifier free on FFMA src)
                        float t0 = qp[4 * i + 0] + mp.x;
                        float t1 = qp[4 * i + 1] + mp.y;
                        float t2 = qp[4 * i + 2] + mp.z;
                        float t3 = qp[4 * i + 3] + mp.w;
                        ac0 = fmaf(w2.x, fabsf(t0), ac0);
                        ac1 = fmaf(w2.y, fabsf(t1), ac1);
                        ac2 = fmaf(w2.z, fabsf(t2), ac2);
                        ac3 = fmaf(w2.w, fabsf(t3), ac3);
                        ax0 = fmaf(qn[4 * i + 0], mx.x, ax0);
                        ax1 = fmaf(qn[4 * i + 1], mx.y, ax1);
                        ax2 = fmaf(qn[4 * i + 2], mx.z, ax2);
                        ax3 = fmaf(qn[4 * i + 3], mx.w, ax3);
                    }
                    float S2 = (ac0 + ac1) + (ac2 + ac3);
                    float S1 = s1qp_lane + s_s1m[w][rl];
                    float z  = fmaf(0.5f, S1 + S2, b2v);
                    float ctx = ((ax0 + ax1) + (ax2 + ax3)) * s_inv[w][r];
                    float sig = 1.0f / (1.0f + __expf(-z));
                    float score = 0.5f * sig + 0.3f * ctx + 0.2f * fresh[c];
                    out4[2 * p2 + r] = score;
                    cmax = fmaxf(cmax, score);
                }
                __syncwarp();
            }
            *(float4*)&g_scores[(size_t)lane * CAP + base + 4 * pp] =
                make_float4(out4[0], out4[1], out4[2], out4[3]);
        }
        g_cmax[lane * NCHUNK + chunk] = cmax;
    }
}

// ---------------- K3: threshold-filter top-16 + gather ----------------
__global__ __launch_bounds__(256) void k3_topk(
    const float* __restrict__ mc, const float* __restrict__ fresh,
    float* __restrict__ out)
{
    __shared__ unsigned s_key[NCHUNK];
    __shared__ unsigned s_tm[256];
    __shared__ unsigned s_tau;
    __shared__ int s_cnt, s_cnt2;
    __shared__ int s_cand[64];
    __shared__ unsigned s_ekey[64];
    __shared__ int s_eidx[64];
    __shared__ int s_sel[TOPK];
    __shared__ float s_val[TOPK];

    int b = blockIdx.x;
    int tid = threadIdx.x;
    int lane = tid & 31;

    unsigned tmax = 0;
    #pragma unroll
    for (int j = 0; j < 8; j++) {
        unsigned k = ordf(g_cmax[b * NCHUNK + tid * 8 + j]);
        s_key[tid * 8 + j] = k;
        tmax = max(tmax, k);
    }
    s_tm[tid] = tmax;
    if (tid == 0) { s_cnt = 0; s_cnt2 = 0; }
    if (tid < 64) s_ekey[tid] = 0u;
    __syncthreads();

    if (tid < 32) {
        unsigned gm = 0;
        #pragma unroll
        for (int j = 0; j < 8; j++) gm = max(gm, s_tm[lane * 8 + j]);
        int rank = 0;
        #pragma unroll
        for (int j = 0; j < 32; j++) {
            unsigned vj = __shfl_sync(FULLM, gm, j);
            rank += (vj > gm) || (vj == gm && j < lane);
        }
        unsigned eq = __ballot_sync(FULLM, rank == 15);
        unsigned tau = __shfl_sync(FULLM, gm, __ffs(eq) - 1);
        if (lane == 0) s_tau = tau;
    }
    __syncthreads();
    unsigned tau = s_tau;

    #pragma unroll
    for (int j = 0; j < 8; j++) {
        int ch = tid * 8 + j;
        if (s_key[ch] >= tau) {
            int p = atomicAdd(&s_cnt, 1);
            if (p < 64) s_cand[p] = ch;
        }
    }
    __syncthreads();
    int cnt = min(s_cnt, 64);

    for (int i = tid; i < cnt * 16; i += 256) {
        int ch = s_cand[i >> 4];
        int gi = ch * 16 + (i & 15);
        unsigned key = ordf(g_scores[(size_t)b * CAP + gi]);
        if (key >= tau) {
            int p = atomicAdd(&s_cnt2, 1);
            if (p < 64) { s_ekey[p] = key; s_eidx[p] = gi; }
        }
    }
    __syncthreads();

    if (tid < 32) {
        for (int k = 0; k < TOPK; k++) {
            unsigned lkey = 0; int lidx = 0x7FFFFFFF; int lpos = -1;
            #pragma unroll
            for (int j = 0; j < 2; j++) {
                int p = lane + 32 * j;
                unsigned kk = s_ekey[p];
                int ii = s_eidx[p];
                if (kk > lkey || (kk == lkey && kk != 0u && ii < lidx)) {
                    lkey = kk; lidx = ii; lpos = p;
                }
            }
            unsigned m = __reduce_max_sync(FULLM, lkey);
            int cand = (lkey == m) ? lidx : 0x7FFFFFFF;
            int gi = __reduce_min_sync(FULLM, cand);
            if (lane == 0) { s_sel[k] = gi; s_val[k] = unordf(m); }
            if (lkey == m && lidx == gi) s_ekey[lpos] = 0u;
            __syncwarp();
        }
    }
    __syncthreads();

    for (int i = tid; i < TOPK * CD; i += 256) {
        int k = i >> 6, h = i & 63;
        out[(size_t)b * (TOPK * CD) + i] = mc[(size_t)s_sel[k] * CD + h];
    }
    if (tid < TOPK) {
        out[NB * TOPK * CD + b * TOPK + tid] = s_val[tid];
        out[NB * TOPK * CD + NB * TOPK + b * TOPK + tid] = fresh[s_sel[tid]];
    }
}

// ---------------- launch ----------------
extern "C" void kernel_launch(void* const* d_in, const int* in_sizes, int n_in,
                              void* d_out, int out_size)
{
    const float* qc    = (const float*)d_in[0];
    const float* qctx  = (const float*)d_in[1];
    const float* mc    = (const float*)d_in[2];
    const float* mctx  = (const float*)d_in[3];
    const float* fresh = (const float*)d_in[4];
    const float* W1    = (const float*)d_in[5];
    const float* b1    = (const float*)d_in[6];
    const float* W2    = (const float*)d_in[7];
    const float* b2    = (const float*)d_in[8];
    float* out = (float*)d_out;

    k0_prep<<<NB, 256>>>(qc, qctx, W1, b1, W2);
    k2_fused<<<NCHUNK / 8, 128>>>(mc, mctx, fresh, W1, W2, b2);
    k3_topk<<<NB, 256>>>(mc, fresh, out);
}

// round 16
// speedup vs baseline: 1.2344x; 1.0397x over previous
#include <cuda_runtime.h>
#include <math.h>

#define CAP 32768
#define NB  32
#define CD  64
#define TOPK 16
#define NCHUNK 2048
#define FULLM 0xFFFFFFFFu
#define ROWPAD 68

typedef unsigned long long ull;

#define FMA2(d, a, b, c) \
    asm("fma.rn.f32x2 %0, %1, %2, %3;" : "=l"(d) : "l"(a), "l"(b), "l"(c))
#define ADD2(d, a, b) \
    asm("add.rn.f32x2 %0, %1, %2;" : "=l"(d) : "l"(a), "l"(b))
#define UNPACK2(lo, hi, x) \
    asm("mov.b64 {%0, %1}, %2;" : "=f"(lo), "=f"(hi) : "l"(x))

// ---------------- scratch ----------------
__device__ float g_qpart[NB * CD];
__device__ float g_qn[NB * CD];
__device__ float g_s1qp[NB];          // w2 . qpart[b]
__device__ float g_scores[NB * CAP];
__device__ float g_cmax[NB * NCHUNK];

__device__ __forceinline__ unsigned ordf(float f) {
    unsigned u = __float_as_uint(f);
    return u ^ ((unsigned)((int)u >> 31) | 0x80000000u);
}
__device__ __forceinline__ float unordf(unsigned k) {
    unsigned u = (k & 0x80000000u) ? (k ^ 0x80000000u) : ~k;
    return __uint_as_float(u);
}

// ---------------- K0: query prep + s1qp (R15, passed) ----------------
__global__ __launch_bounds__(256) void k0_prep(
    const float* __restrict__ qc, const float* __restrict__ qctx,
    const float* __restrict__ W1, const float* __restrict__ b1,
    const float* __restrict__ W2)
{
    __shared__ float sq[64];
    __shared__ float sp[4][64];
    __shared__ float sps[2];
    __shared__ float sd[2];
    int b = blockIdx.x, tid = threadIdx.x;
    int h = tid & 63, part = tid >> 6;

    if (tid < 64) sq[tid] = qc[b * CD + tid];
    float v = (tid < 64) ? qctx[b * CD + tid] : 0.0f;
    __syncthreads();

    float s = 0.0f;
    #pragma unroll
    for (int j = 0; j < 16; j++) {
        int d = part * 16 + j;
        s = fmaf(sq[d], W1[d * CD + h], s);
    }
    sp[part][h] = s;

    float ss = v * v;
    #pragma unroll
    for (int o = 16; o; o >>= 1) ss += __shfl_xor_sync(FULLM, ss, o);
    if (tid == 0)  sps[0] = ss;
    if (tid == 32) sps[1] = ss;
    __syncthreads();

    if (tid < 64) {
        float qv = sp[0][tid] + sp[1][tid] + sp[2][tid] + sp[3][tid] + b1[tid];
        g_qpart[b * CD + tid] = qv;
        float inv = 1.0f / fmaxf(sqrtf(sps[0] + sps[1]), 1e-8f);
        g_qn[b * CD + tid] = v * inv;
        float c1 = qv * W2[tid];
        #pragma unroll
        for (int o = 16; o; o >>= 1) c1 += __shfl_xor_sync(FULLM, c1, o);
        if (tid == 0)  sd[0] = c1;
        if (tid == 32) sd[1] = c1;
    }
    __syncthreads();
    if (tid == 0) g_s1qp[b] = sd[0] + sd[1];
}

// ---------------- K2: scalar GEMM + packed abs-trick scoring ----------------
__global__ __launch_bounds__(128, 1) void k2_fused(
    const float* __restrict__ mc, const float* __restrict__ mctx,
    const float* __restrict__ fresh,
    const float* __restrict__ W1, const float* __restrict__ W2,
    const float* __restrict__ b2p)
{
    __shared__ float  sB[64 * 64];
    __shared__ float  sA[4][16 * ROWPAD];
    __shared__ float4 s_mx[4][2][16];
    __shared__ float4 s_w2[16];
    __shared__ float  s_inv[4][2];
    __shared__ float  s_s1m[4][16];

    int tid = threadIdx.x, w = tid >> 5, lane = tid & 31;

    {
        const float4* src = (const float4*)(W1 + 64 * 64);
        float4* dst = (float4*)sB;
        for (int i = tid; i < 1024; i += 128) dst[i] = src[i];
    }
    if (tid < 16) s_w2[tid] = ((const float4*)W2)[tid];
    __syncthreads();

    float b2v = b2p[0];
    float s1qp_lane = g_s1qp[lane];

    // per-lane query vectors as packed pairs (lane = query b)
    ull qp2[32], qn2[32];
    {
        const ulonglong2* a4 = (const ulonglong2*)(g_qpart + lane * CD);
        const ulonglong2* n4 = (const ulonglong2*)(g_qn + lane * CD);
        #pragma unroll
        for (int i = 0; i < 16; i++) {
            ulonglong2 a = a4[i];
            qp2[2 * i] = a.x; qp2[2 * i + 1] = a.y;
            ulonglong2 n = n4[i];
            qn2[2 * i] = n.x; qn2[2 * i + 1] = n.y;
        }
    }

    int rg = lane >> 3;
    int hg = lane & 7;
    int half = lane >> 4, q = lane & 15;

    #pragma unroll 1
    for (int it = 0; it < 2; it++) {
        int chunk = blockIdx.x * 8 + w * 2 + it;
        int base = chunk * 16;

        __syncwarp();
        // stage mc rows [16][64]
        {
            const float4* mcp = (const float4*)(mc + (size_t)base * CD);
            #pragma unroll
            for (int j = 0; j < 8; j++) {
                int idx = lane + 32 * j;
                int r = idx >> 4, cc = idx & 15;
                *(float4*)&sA[w][r * ROWPAD + cc * 4] = mcp[idx];
            }
        }
        __syncwarp();

        // GEMM (scalar, known-good): m_part[r][h] = sum_d mc[r][d] * W1b[d][h]
        float acc[4][8];
        #pragma unroll
        for (int r = 0; r < 4; r++)
            #pragma unroll
            for (int j = 0; j < 8; j++) acc[r][j] = 0.0f;

        #pragma unroll 4
        for (int d4 = 0; d4 < 16; d4++) {
            float4 a[4];
            #pragma unroll
            for (int r = 0; r < 4; r++)
                a[r] = *(const float4*)&sA[w][(rg * 4 + r) * ROWPAD + d4 * 4];
            #pragma unroll
            for (int k = 0; k < 4; k++) {
                int d = 4 * d4 + k;
                float4 blo = *(const float4*)&sB[d * 64 + hg * 8];
                float4 bhi = *(const float4*)&sB[d * 64 + hg * 8 + 4];
                #pragma unroll
                for (int r = 0; r < 4; r++) {
                    float av = (k == 0) ? a[r].x : (k == 1) ? a[r].y : (k == 2) ? a[r].z : a[r].w;
                    acc[r][0] = fmaf(av, blo.x, acc[r][0]);
                    acc[r][1] = fmaf(av, blo.y, acc[r][1]);
                    acc[r][2] = fmaf(av, blo.z, acc[r][2]);
                    acc[r][3] = fmaf(av, blo.w, acc[r][3]);
                    acc[r][4] = fmaf(av, bhi.x, acc[r][4]);
                    acc[r][5] = fmaf(av, bhi.y, acc[r][5]);
                    acc[r][6] = fmaf(av, bhi.z, acc[r][6]);
                    acc[r][7] = fmaf(av, bhi.w, acc[r][7]);
                }
            }
        }
        __syncwarp();
        // write m_part + s1m[r] = w2 . m_part[r] from resident accumulators
        {
            float4 w2lo = s_w2[hg * 2];
            float4 w2hi = s_w2[hg * 2 + 1];
            #pragma unroll
            for (int r = 0; r < 4; r++) {
                *(float4*)&sA[w][(rg * 4 + r) * ROWPAD + hg * 8] =
                    make_float4(acc[r][0], acc[r][1], acc[r][2], acc[r][3]);
                *(float4*)&sA[w][(rg * 4 + r) * ROWPAD + hg * 8 + 4] =
                    make_float4(acc[r][4], acc[r][5], acc[r][6], acc[r][7]);
                float sp = acc[r][0] * w2lo.x;
                sp = fmaf(acc[r][1], w2lo.y, sp);
                sp = fmaf(acc[r][2], w2lo.z, sp);
                sp = fmaf(acc[r][3], w2lo.w, sp);
                sp = fmaf(acc[r][4], w2hi.x, sp);
                sp = fmaf(acc[r][5], w2hi.y, sp);
                sp = fmaf(acc[r][6], w2hi.z, sp);
                sp = fmaf(acc[r][7], w2hi.w, sp);
                sp += __shfl_xor_sync(FULLM, sp, 1);
                sp += __shfl_xor_sync(FULLM, sp, 2);
                sp += __shfl_xor_sync(FULLM, sp, 4);
                if (hg == 0) s_s1m[w][rg * 4 + r] = sp;
            }
        }
        __syncwarp();

        // scoring: 16 rows, 2 at a time; lane = query b; packed f32x2 + and-abs
        float4 nmx = ((const float4*)(mctx + (size_t)(base + half) * CD))[q];
        float cmax = -1e30f;

        #pragma unroll 1
        for (int pp = 0; pp < 4; pp++) {
            float out4[4];
            #pragma unroll
            for (int p2 = 0; p2 < 2; p2++) {
                int p = 2 * pp + p2;
                int c0 = base + 2 * p;
                s_mx[w][half][q] = nmx;
                float ssn = nmx.x * nmx.x + nmx.y * nmx.y + nmx.z * nmx.z + nmx.w * nmx.w;
                ssn += __shfl_xor_sync(FULLM, ssn, 1);
                ssn += __shfl_xor_sync(FULLM, ssn, 2);
                ssn += __shfl_xor_sync(FULLM, ssn, 4);
                ssn += __shfl_xor_sync(FULLM, ssn, 8);
                if (q == 0) s_inv[w][half] = 1.0f / fmaxf(sqrtf(ssn), 1e-8f);
                __syncwarp();
                if (p < 7)
                    nmx = ((const float4*)(mctx + (size_t)(c0 + 2 + half) * CD))[q];
                #pragma unroll
                for (int r = 0; r < 2; r++) {
                    int c = c0 + r;
                    int rl = 2 * p + r;
                    ull ac01 = 0ull, ac23 = 0ull;   // S2 pairs
                    ull ax01 = 0ull, ax23 = 0ull;   // ctx pairs
                    #pragma unroll
                    for (int i = 0; i < 16; i++) {
                        ulonglong2 mp2 = *(const ulonglong2*)&sA[w][rl * ROWPAD + 4 * i];
                        ulonglong2 mx2 = *(const ulonglong2*)&s_mx[w][r][i];
                        ulonglong2 w22 = *(const ulonglong2*)&s_w2[i];
                        ull t01; ADD2(t01, qp2[2 * i], mp2.x);
                        ull t23; ADD2(t23, qp2[2 * i + 1], mp2.y);
                        ull a01 = t01 & 0x7FFFFFFF7FFFFFFFull;   // |.| packed (alu pipe)
                        ull a23 = t23 & 0x7FFFFFFF7FFFFFFFull;
                        FMA2(ac01, w22.x, a01, ac01);
                        FMA2(ac23, w22.y, a23, ac23);
                        FMA2(ax01, qn2[2 * i], mx2.x, ax01);
                        FMA2(ax23, qn2[2 * i + 1], mx2.y, ax23);
                    }
                    float s2a, s2b, s2c, s2d, xa, xb, xc, xd;
                    UNPACK2(s2a, s2b, ac01);
                    UNPACK2(s2c, s2d, ac23);
                    UNPACK2(xa, xb, ax01);
                    UNPACK2(xc, xd, ax23);
                    float S2 = (s2a + s2b) + (s2c + s2d);
                    float S1 = s1qp_lane + s_s1m[w][rl];
                    float z  = fmaf(0.5f, S1 + S2, b2v);
                    float ctx = ((xa + xb) + (xc + xd)) * s_inv[w][r];
                    float sig = 1.0f / (1.0f + __expf(-z));
                    float score = 0.5f * sig + 0.3f * ctx + 0.2f * fresh[c];
                    out4[2 * p2 + r] = score;
                    cmax = fmaxf(cmax, score);
                }
                __syncwarp();
            }
            *(float4*)&g_scores[(size_t)lane * CAP + base + 4 * pp] =
                make_float4(out4[0], out4[1], out4[2], out4[3]);
        }
        g_cmax[lane * NCHUNK + chunk] = cmax;
    }
}

// ---------------- K3: threshold-filter top-16 + gather ----------------
__global__ __launch_bounds__(256) void k3_topk(
    const float* __restrict__ mc, const float* __restrict__ fresh,
    float* __restrict__ out)
{
    __shared__ unsigned s_key[NCHUNK];
    __shared__ unsigned s_tm[256];
    __shared__ unsigned s_tau;
    __shared__ int s_cnt, s_cnt2;
    __shared__ int s_cand[64];
    __shared__ unsigned s_ekey[64];
    __shared__ int s_eidx[64];
    __shared__ int s_sel[TOPK];
    __shared__ float s_val[TOPK];

    int b = blockIdx.x;
    int tid = threadIdx.x;
    int lane = tid & 31;

    unsigned tmax = 0;
    #pragma unroll
    for (int j = 0; j < 8; j++) {
        unsigned k = ordf(g_cmax[b * NCHUNK + tid * 8 + j]);
        s_key[tid * 8 + j] = k;
        tmax = max(tmax, k);
    }
    s_tm[tid] = tmax;
    if (tid == 0) { s_cnt = 0; s_cnt2 = 0; }
    if (tid < 64) s_ekey[tid] = 0u;
    __syncthreads();

    if (tid < 32) {
        unsigned gm = 0;
        #pragma unroll
        for (int j = 0; j < 8; j++) gm = max(gm, s_tm[lane * 8 + j]);
        int rank = 0;
        #pragma unroll
        for (int j = 0; j < 32; j++) {
            unsigned vj = __shfl_sync(FULLM, gm, j);
            rank += (vj > gm) || (vj == gm && j < lane);
        }
        unsigned eq = __ballot_sync(FULLM, rank == 15);
        unsigned tau = __shfl_sync(FULLM, gm, __ffs(eq) - 1);
        if (lane == 0) s_tau = tau;
    }
    __syncthreads();
    unsigned tau = s_tau;

    #pragma unroll
    for (int j = 0; j < 8; j++) {
        int ch = tid * 8 + j;
        if (s_key[ch] >= tau) {
            int p = atomicAdd(&s_cnt, 1);
            if (p < 64) s_cand[p] = ch;
        }
    }
    __syncthreads();
    int cnt = min(s_cnt, 64);

    for (int i = tid; i < cnt * 16; i += 256) {
        int ch = s_cand[i >> 4];
        int gi = ch * 16 + (i & 15);
        unsigned key = ordf(g_scores[(size_t)b * CAP + gi]);
        if (key >= tau) {
            int p = atomicAdd(&s_cnt2, 1);
            if (p < 64) { s_ekey[p] = key; s_eidx[p] = gi; }
        }
    }
    __syncthreads();

    if (tid < 32) {
        for (int k = 0; k < TOPK; k++) {
            unsigned lkey = 0; int lidx = 0x7FFFFFFF; int lpos = -1;
            #pragma unroll
            for (int j = 0; j < 2; j++) {
                int p = lane + 32 * j;
                unsigned kk = s_ekey[p];
                int ii = s_eidx[p];
                if (kk > lkey || (kk == lkey && kk != 0u && ii < lidx)) {
                    lkey = kk; lidx = ii; lpos = p;
                }
            }
            unsigned m = __reduce_max_sync(FULLM, lkey);
            int cand = (lkey == m) ? lidx : 0x7FFFFFFF;
            int gi = __reduce_min_sync(FULLM, cand);
            if (lane == 0) { s_sel[k] = gi; s_val[k] = unordf(m); }
            if (lkey == m && lidx == gi) s_ekey[lpos] = 0u;
            __syncwarp();
        }
    }
    __syncthreads();

    for (int i = tid; i < TOPK * CD; i += 256) {
        int k = i >> 6, h = i & 63;
        out[(size_t)b * (TOPK * CD) + i] = mc[(size_t)s_sel[k] * CD + h];
    }
    if (tid < TOPK) {
        out[NB * TOPK * CD + b * TOPK + tid] = s_val[tid];
        out[NB * TOPK * CD + NB * TOPK + b * TOPK + tid] = fresh[s_sel[tid]];
    }
}

// ---------------- launch ----------------
extern "C" void kernel_launch(void* const* d_in, const int* in_sizes, int n_in,
                              void* d_out, int out_size)
{
    const float* qc    = (const float*)d_in[0];
    const float* qctx  = (const float*)d_in[1];
    const float* mc    = (const float*)d_in[2];
    const float* mctx  = (const float*)d_in[3];
    const float* fresh = (const float*)d_in[4];
    const float* W1    = (const float*)d_in[5];
    const float* b1    = (const float*)d_in[6];
    const float* W2    = (const float*)d_in[7];
    const float* b2    = (const float*)d_in[8];
    float* out = (float*)d_out;

    k0_prep<<<NB, 256>>>(qc, qctx, W1, b1, W2);
    k2_fused<<<NCHUNK / 8, 128>>>(mc, mctx, fresh, W1, W2, b2);
    k3_topk<<<NB, 256>>>(mc, fresh, out);
}